// round 7
// baseline (speedup 1.0000x reference)
#include <cuda_runtime.h>
#include <cuda_fp16.h>
#include <math.h>

#define DIMV 2048
#define NTR  4096
#define MDEVR 8192
#define TST  500
#define ETA  0.1f
#define NTHREADS 256
#define NWARPS 8
#define BDEV 10           /* dev-loss batching factor; TST % BDEV == 0 */

#define S_GRAD_F   1.7179869184e10f   /* 2^34 */
#define INV_SGRAD  5.8207660913e-11f  /* 2^-34 */
#define S_DEV_F    4.294967296e9f     /* 2^32 */
#define INV_SDEV   2.3283064365e-10f  /* 2^-32 */

// Persistent device state (static allocation — no cudaMalloc anywhere)
__device__ unsigned long long g_gradacc[DIMV];   // fixed-point running totals
__device__ unsigned long long g_devaccB[BDEV];   // per-batch-slot dev totals
__device__ unsigned long long g_devacc;          // final-eval total
__device__ unsigned           g_arrive;
__device__ __half g_xn_h[(size_t)NTR * DIMV];     // 16.8 MB
__device__ __half g_dxn_h[(size_t)MDEVR * DIMV];  // 33.6 MB

// ---------------------------------------------------------------------------
__global__ void ak_init(float* __restrict__ out, int out_size) {
    int i = blockIdx.x * blockDim.x + threadIdx.x;
    if (i == 0) { g_arrive = 0u; g_devacc = 0ull; }
    if (i < BDEV) g_devaccB[i] = 0ull;
    if (i < DIMV) g_gradacc[i] = 0ull;
    for (int j = TST + 1 + i; j < out_size; j += gridDim.x * blockDim.x)
        out[j] = 0.0f;
}

__global__ void ak_convert(const float* __restrict__ xn,
                           const float* __restrict__ dxn) {
    const size_t n4  = (size_t)NTR * DIMV / 4;
    const size_t m4  = (size_t)MDEVR * DIMV / 4;
    const float4* s0 = (const float4*)xn;
    const float4* s1 = (const float4*)dxn;
    __half2* d0 = (__half2*)g_xn_h;
    __half2* d1 = (__half2*)g_dxn_h;
    size_t stride = (size_t)gridDim.x * blockDim.x;
    for (size_t i = blockIdx.x * (size_t)blockDim.x + threadIdx.x; i < n4; i += stride) {
        float4 v = s0[i];
        d0[2*i+0] = __floats2half2_rn(v.x, v.y);
        d0[2*i+1] = __floats2half2_rn(v.z, v.w);
    }
    for (size_t i = blockIdx.x * (size_t)blockDim.x + threadIdx.x; i < m4; i += stride) {
        float4 v = s1[i];
        d1[2*i+0] = __floats2half2_rn(v.x, v.y);
        d1[2*i+1] = __floats2half2_rn(v.z, v.w);
    }
}

__device__ __forceinline__ void grid_barrier(unsigned nb) {
    __syncthreads();
    if (threadIdx.x == 0) {
        __threadfence();
        unsigned old = atomicAdd(&g_arrive, 1u);
        unsigned target = (old / nb + 1u) * nb;
        while (*((volatile unsigned*)&g_arrive) < target) { }
        __threadfence();
    }
    __syncthreads();
}

__device__ __forceinline__ float dev_loss_elem(float z, float y) {
    return fmaxf(z, 0.0f) - y * z + log1pf(expf(-fabsf(z)));
}

__device__ __forceinline__ void dot8h(__half2* acc2, const uint4& u, const __half2* th2j) {
    const __half2* h = (const __half2*)&u;
    acc2[0] = __hfma2(h[0], th2j[0], acc2[0]);
    acc2[1] = __hfma2(h[1], th2j[1], acc2[1]);
    acc2[2] = __hfma2(h[2], th2j[2], acc2[2]);
    acc2[3] = __hfma2(h[3], th2j[3], acc2[3]);
}

__device__ __forceinline__ void grad8h(__half2* gj, const uint4& u, __half2 ch2) {
    const __half2* h = (const __half2*)&u;
    gj[0] = __hfma2(ch2, h[0], gj[0]);
    gj[1] = __hfma2(ch2, h[1], gj[1]);
    gj[2] = __hfma2(ch2, h[2], gj[2]);
    gj[3] = __hfma2(ch2, h[3], gj[3]);
}

__device__ __forceinline__ float acc4_to_float(const __half2* a) {
    float2 f0 = __half22float2(a[0]);
    float2 f1 = __half22float2(a[1]);
    float2 f2 = __half22float2(a[2]);
    float2 f3 = __half22float2(a[3]);
    return (f0.x + f0.y) + (f1.x + f1.y) + (f2.x + f2.y) + (f3.x + f3.y);
}

// R contiguous train rows: dot + interleaved reduce + fused grad accumulation.
// After the butterfly, z[r] is identical on all lanes.
template<int R>
__device__ __forceinline__ void train_chunk(
    int n0, int lane, int t, const __half2* th2, __half2* hacc,
    const float* __restrict__ yn, const float* __restrict__ alphas)
{
    const uint4* xp[R];
#pragma unroll
    for (int r = 0; r < R; r++)
        xp[r] = (const uint4*)(g_xn_h + (size_t)(n0 + r) * DIMV);
    const __half2 hz = __float2half2_rn(0.0f);
    __half2 a[R][4];
#pragma unroll
    for (int r = 0; r < R; r++) { a[r][0]=hz; a[r][1]=hz; a[r][2]=hz; a[r][3]=hz; }
#pragma unroll
    for (int j = 0; j < 8; j++) {
#pragma unroll
        for (int r = 0; r < R; r++) {
            uint4 u = xp[r][j*32+lane];
            dot8h(a[r], u, th2 + j*4);
        }
    }
    float z[R];
#pragma unroll
    for (int r = 0; r < R; r++) z[r] = acc4_to_float(a[r]);
#pragma unroll
    for (int o = 16; o; o >>= 1) {
#pragma unroll
        for (int r = 0; r < R; r++)
            z[r] += __shfl_xor_sync(0xffffffffu, z[r], o);
    }
    __half2 ch[R];
#pragma unroll
    for (int r = 0; r < R; r++) {
        float s = 1.0f / (1.0f + expf(-z[r]));
        float c = alphas[(size_t)t * NTR + (n0 + r)] * (s - yn[n0 + r]);
        ch[r] = __float2half2_rn(c);
    }
#pragma unroll
    for (int j = 0; j < 8; j++) {
#pragma unroll
        for (int r = 0; r < R; r++) {
            uint4 u = xp[r][j*32+lane];   // L1 hits
            grad8h(hacc + j*4, u, ch[r]);
        }
    }
}

// Batched dev pass over R(=2 or 1) rows x BDEV thetas from the smem ring.
// db[b] accumulates full (all-lane-identical) loss sums.
template<int R>
__device__ __forceinline__ void dev_batch_chunk(
    int m0, int lane, const __half* s_ring, float* db,
    const float* __restrict__ dyn)
{
    const __half2 hz = __float2half2_rn(0.0f);
    uint4 x[R][8];
#pragma unroll
    for (int r = 0; r < R; r++) {
        const uint4* p = (const uint4*)(g_dxn_h + (size_t)(m0 + r) * DIMV);
#pragma unroll
        for (int j = 0; j < 8; j++) x[r][j] = p[j*32+lane];
    }
    float z[R][BDEV];
#pragma unroll
    for (int b = 0; b < BDEV; b++) {
        const uint4* tr = (const uint4*)(s_ring + (size_t)b * DIMV);
        __half2 a[R][4];
#pragma unroll
        for (int r = 0; r < R; r++) { a[r][0]=hz; a[r][1]=hz; a[r][2]=hz; a[r][3]=hz; }
#pragma unroll
        for (int j = 0; j < 8; j++) {
            uint4 th = tr[j*32+lane];              // LDS.128, conflict-free
#pragma unroll
            for (int r = 0; r < R; r++)
                dot8h(a[r], x[r][j], (const __half2*)&th);
        }
#pragma unroll
        for (int r = 0; r < R; r++) z[r][b] = acc4_to_float(a[r]);
    }
#pragma unroll
    for (int o = 16; o; o >>= 1) {
#pragma unroll
        for (int b = 0; b < BDEV; b++)
#pragma unroll
            for (int r = 0; r < R; r++)
                z[r][b] += __shfl_xor_sync(0xffffffffu, z[r][b], o);
    }
#pragma unroll
    for (int b = 0; b < BDEV; b++) {
#pragma unroll
        for (int r = 0; r < R; r++)
            db[b] += dev_loss_elem(z[r][b], dyn[m0 + r]);
    }
}

// Single-theta dev chunk for the final evaluation (theta in registers).
template<int R>
__device__ __forceinline__ float dev_chunk(
    int m0, int lane, const __half2* th2, const float* __restrict__ dyn)
{
    const uint4* xp[R];
#pragma unroll
    for (int r = 0; r < R; r++)
        xp[r] = (const uint4*)(g_dxn_h + (size_t)(m0 + r) * DIMV);
    const __half2 hz = __float2half2_rn(0.0f);
    __half2 a[R][4];
#pragma unroll
    for (int r = 0; r < R; r++) { a[r][0]=hz; a[r][1]=hz; a[r][2]=hz; a[r][3]=hz; }
#pragma unroll
    for (int j = 0; j < 8; j++) {
#pragma unroll
        for (int r = 0; r < R; r++) {
            uint4 u = xp[r][j*32+lane];
            dot8h(a[r], u, th2 + j*4);
        }
    }
    float z[R];
#pragma unroll
    for (int r = 0; r < R; r++) z[r] = acc4_to_float(a[r]);
#pragma unroll
    for (int o = 16; o; o >>= 1) {
#pragma unroll
        for (int r = 0; r < R; r++)
            z[r] += __shfl_xor_sync(0xffffffffu, z[r], o);
    }
    float s = 0.0f;
#pragma unroll
    for (int r = 0; r < R; r++) s += dev_loss_elem(z[r], dyn[m0 + r]);
    return s;
}

// ---------------------------------------------------------------------------
__global__ void __launch_bounds__(NTHREADS, 1)
ak_train(const float* __restrict__ theta0,
         const float* __restrict__ yn,  const float* __restrict__ dyn,
         const float* __restrict__ alphas,
         float* __restrict__ out, int out_size) {
    extern __shared__ char smc[];
    float*  s_theta = (float*)smc;                               // 8 KB
    __half* s_grad  = (__half*)(smc + DIMV * 4);                 // 32 KB
    __half* s_ring  = (__half*)(smc + DIMV * 4 + NWARPS * DIMV * 2);   // 40 KB
    float*  s_devB  = (float*)(smc + DIMV * 4 + NWARPS * DIMV * 2
                               + (size_t)BDEV * DIMV * 2);        // NWARPS*BDEV
    float*  s_dev   = s_devB + NWARPS * BDEV;                     // NWARPS
    long long* s_devprev = (long long*)(s_dev + NWARPS);          // BDEV

    const int tid  = threadIdx.x;
    const int lane = tid & 31;
    const int w    = tid >> 5;
    const int cta  = blockIdx.x;
    const int ncta = gridDim.x;

    const int rb = (int)(((long long)cta * NTR) / ncta);
    const int re = (int)(((long long)(cta + 1) * NTR) / ncta);
    const int mb = (int)(((long long)cta * MDEVR) / ncta);
    const int me = (int)(((long long)(cta + 1) * MDEVR) / ncta);
    const int twb = rb + (int)(((long long)(re - rb) * w) / NWARPS);
    const int twe = rb + (int)(((long long)(re - rb) * (w + 1)) / NWARPS);
    const int dwb = mb + (int)(((long long)(me - mb) * w) / NWARPS);
    const int dwe = mb + (int)(((long long)(me - mb) * (w + 1)) / NWARPS);

    for (int d = tid; d < DIMV; d += NTHREADS) s_theta[d] = theta0[d];
    if (tid < BDEV) s_devprev[tid] = 0ll;
    __syncthreads();

    long long prev[8];
#pragma unroll
    for (int i = 0; i < 8; i++) prev[i] = 0ll;
    float isum = 0.0f;   // cta0/tid0 only

    __half2 th2[32];
    const __half2 hz = __float2half2_rn(0.0f);

    for (int t = 0; t < TST; ++t) {
        const bool pass = ((t % BDEV) == BDEV - 1);
        // ---- theta(smem fp32) -> th2 registers (identical in every warp)
        {
            const float4* t4 = (const float4*)s_theta;
#pragma unroll
            for (int j = 0; j < 8; j++) {
                float4 v0 = t4[(j*32+lane)*2 + 0];
                float4 v1 = t4[(j*32+lane)*2 + 1];
                th2[j*4+0] = __floats2half2_rn(v0.x, v0.y);
                th2[j*4+1] = __floats2half2_rn(v0.z, v0.w);
                th2[j*4+2] = __floats2half2_rn(v1.x, v1.y);
                th2[j*4+3] = __floats2half2_rn(v1.z, v1.w);
            }
        }
        // ---- snapshot theta_t (pre-update) into ring slot t%BDEV (warp 0)
        if (w == 0) {
            uint4* rp = (uint4*)(s_ring + (size_t)(t % BDEV) * DIMV);
#pragma unroll
            for (int j = 0; j < 8; j++) {
                uint4 u;
                ((__half2*)&u)[0] = th2[j*4+0];
                ((__half2*)&u)[1] = th2[j*4+1];
                ((__half2*)&u)[2] = th2[j*4+2];
                ((__half2*)&u)[3] = th2[j*4+3];
                rp[j*32+lane] = u;
            }
        }

        // ---- train rows (quad -> pair -> single)
        __half2 hacc[32];
#pragma unroll
        for (int j = 0; j < 32; j++) hacc[j] = hz;
        {
            int n = twb;
            for (; n + 4 <= twe; n += 4) train_chunk<4>(n, lane, t, th2, hacc, yn, alphas);
            if (n + 2 <= twe) { train_chunk<2>(n, lane, t, th2, hacc, yn, alphas); n += 2; }
            if (n < twe)        train_chunk<1>(n, lane, t, th2, hacc, yn, alphas);
        }
        {
            uint4* gp4 = (uint4*)(s_grad + (size_t)w * DIMV);
#pragma unroll
            for (int j = 0; j < 8; j++) {
                uint4 u;
                ((__half2*)&u)[0] = hacc[j*4+0];
                ((__half2*)&u)[1] = hacc[j*4+1];
                ((__half2*)&u)[2] = hacc[j*4+2];
                ((__half2*)&u)[3] = hacc[j*4+3];
                gp4[j*32+lane] = u;
            }
        }

        // ---- batched dev pass every BDEV steps (ring holds theta_{t-9..t})
        if (pass) {
            __syncthreads();   // ring slot t%BDEV (warp0) visible to all warps
            float db[BDEV];
#pragma unroll
            for (int b = 0; b < BDEV; b++) db[b] = 0.0f;
            int m = dwb;
            for (; m + 2 <= dwe; m += 2) dev_batch_chunk<2>(m, lane, s_ring, db, dyn);
            if (m < dwe)                 dev_batch_chunk<1>(m, lane, s_ring, db, dyn);
            if (lane == 0) {
#pragma unroll
                for (int b = 0; b < BDEV; b++) s_devB[w * BDEV + b] = db[b];
            }
        }
        __syncthreads();

        // ---- CTA reduce + fixed-point atomics into running totals
        if (pass && tid < BDEV) {
            float s = 0.0f;
#pragma unroll
            for (int ww = 0; ww < NWARPS; ww++) s += s_devB[ww * BDEV + tid];
            atomicAdd(&g_devaccB[tid], (unsigned long long)llrintf(s * S_DEV_F));
        }
        {
            const __half2* sg2 = (const __half2*)s_grad;
#pragma unroll
            for (int i = 0; i < 4; i++) {
                int idx = tid + i * NTHREADS;
                float2 s = make_float2(0.0f, 0.0f);
#pragma unroll
                for (int ww = 0; ww < NWARPS; ww++) {
                    float2 f = __half22float2(sg2[ww * (DIMV/2) + idx]);
                    s.x += f.x; s.y += f.y;
                }
                atomicAdd(&g_gradacc[2*idx+0], (unsigned long long)llrintf(s.x * S_GRAD_F));
                atomicAdd(&g_gradacc[2*idx+1], (unsigned long long)llrintf(s.y * S_GRAD_F));
            }
        }

        grid_barrier((unsigned)ncta);

        // ---- apply delta; CTA0 publishes the batch losses (atomics now visible)
        {
            const long long* ga = (const long long*)g_gradacc;
#pragma unroll
            for (int i = 0; i < 8; i++) {
                int d = tid * 8 + i;
                long long v = ga[d];
                float g = (float)(v - prev[i]) * INV_SGRAD;
                prev[i] = v;
                s_theta[d] -= ETA * g;
            }
            if (pass && cta == 0 && tid == 0) {
                int tb0 = t - (BDEV - 1);
#pragma unroll
                for (int b = 0; b < BDEV; b++) {
                    long long v = (long long)g_devaccB[b];
                    float Lb = (float)(v - s_devprev[b]) * INV_SDEV * (1.0f / MDEVR);
                    s_devprev[b] = v;
                    int ts = tb0 + b;
                    if (1 + ts < out_size) out[1 + ts] = Lb;
                    if (ts >= 1) isum += Lb;
                }
            }
        }
        __syncthreads();
    }

    // ---- final dev eval at theta_T; finalize scalar loss
    {
        const float4* t4 = (const float4*)s_theta;
#pragma unroll
        for (int j = 0; j < 8; j++) {
            float4 v0 = t4[(j*32+lane)*2 + 0];
            float4 v1 = t4[(j*32+lane)*2 + 1];
            th2[j*4+0] = __floats2half2_rn(v0.x, v0.y);
            th2[j*4+1] = __floats2half2_rn(v0.z, v0.w);
            th2[j*4+2] = __floats2half2_rn(v1.x, v1.y);
            th2[j*4+3] = __floats2half2_rn(v1.z, v1.w);
        }
        float dsum = 0.0f;
        {
            int m = dwb;
            for (; m + 4 <= dwe; m += 4) dsum += dev_chunk<4>(m, lane, th2, dyn);
            if (m + 2 <= dwe) { dsum += dev_chunk<2>(m, lane, th2, dyn); m += 2; }
            if (m < dwe)        dsum += dev_chunk<1>(m, lane, th2, dyn);
        }
        if (lane == 0) s_dev[w] = dsum;   // already fully reduced on all lanes
        __syncthreads();
        if (tid == 0) {
            float s = 0.0f;
#pragma unroll
            for (int i = 0; i < NWARPS; i++) s += s_dev[i];
            atomicAdd(&g_devacc, (unsigned long long)llrintf(s * S_DEV_F));
        }
        grid_barrier((unsigned)ncta);
        if (cta == 0 && tid == 0) {
            float LT = (float)((long long)g_devacc) * INV_SDEV * (1.0f / MDEVR);
            if (out_size > 0) out[0] = (isum + LT) / (float)TST;
        }
    }
}

// ---------------------------------------------------------------------------
extern "C" void kernel_launch(void* const* d_in, const int* in_sizes, int n_in,
                              void* d_out, int out_size) {
    const float *theta = nullptr, *alphas = nullptr, *xn = nullptr,
                *yn = nullptr, *dxn = nullptr, *dyn = nullptr;
    for (int i = 0; i < n_in; i++) {
        switch (in_sizes[i]) {
            case DIMV:         theta  = (const float*)d_in[i]; break;
            case TST * NTR:    alphas = (const float*)d_in[i]; break;
            case NTR * DIMV:   xn     = (const float*)d_in[i]; break;
            case NTR:          yn     = (const float*)d_in[i]; break;
            case MDEVR * DIMV: dxn    = (const float*)d_in[i]; break;
            case MDEVR:        dyn    = (const float*)d_in[i]; break;
            default: break;
        }
    }
    float* out = (float*)d_out;

    int dev = 0;
    cudaGetDevice(&dev);
    int nsm = 148;
    cudaDeviceGetAttribute(&nsm, cudaDevAttrMultiProcessorCount, dev);
    int ncta = nsm < 1 ? 1 : nsm;

    size_t smem = (size_t)DIMV * 4                      // s_theta
                + (size_t)NWARPS * DIMV * 2             // s_grad
                + (size_t)BDEV * DIMV * 2               // s_ring
                + (size_t)(NWARPS * BDEV + NWARPS) * 4  // s_devB + s_dev
                + (size_t)BDEV * 8;                     // s_devprev  (~81.4 KB)
    cudaFuncSetAttribute(ak_train, cudaFuncAttributeMaxDynamicSharedMemorySize,
                         (int)smem);

    ak_init<<<(DIMV + 255) / 256, 256>>>(out, out_size);
    ak_convert<<<4 * nsm, 256>>>(xn, dxn);
    ak_train<<<ncta, NTHREADS, smem>>>(theta, yn, dyn, alphas, out, out_size);
}

// round 8
// speedup vs baseline: 1.1519x; 1.1519x over previous
#include <cuda_runtime.h>
#include <cuda_fp16.h>
#include <math.h>

#define DIMV 2048
#define NTR  4096
#define MDEVR 8192
#define TST  500
#define ETA  0.1f
#define NTHREADS 512
#define NWARPS 16

#define S_GRAD_F   1.7179869184e10f   /* 2^34 */
#define INV_SGRAD  5.8207660913e-11f  /* 2^-34 */
#define S_DEV_F    4.294967296e9f     /* 2^32 */
#define INV_SDEV   2.3283064365e-10f  /* 2^-32 */

// Persistent device state (static allocation, zero-initialized at load).
// g_arrive is never reset: the barrier leaves it a multiple of gridDim.x.
__device__ unsigned long long g_gradacc[DIMV];
__device__ unsigned long long g_devacc;
__device__ unsigned           g_arrive;
__device__ __half g_xn_h[(size_t)NTR * DIMV];     // 16.8 MB
__device__ __half g_dxn_h[(size_t)MDEVR * DIMV];  // 33.6 MB

__device__ __forceinline__ void grid_barrier(unsigned nb) {
    __syncthreads();
    if (threadIdx.x == 0) {
        __threadfence();
        unsigned old = atomicAdd(&g_arrive, 1u);
        unsigned target = (old / nb + 1u) * nb;
        while (*((volatile unsigned*)&g_arrive) < target) { }
        __threadfence();
    }
    __syncthreads();
}

__device__ __forceinline__ float dev_loss_elem(float z, float y) {
    return fmaxf(z, 0.0f) - y * z + log1pf(expf(-fabsf(z)));
}

__device__ __forceinline__ void dot8h(__half2* acc2, const uint4& u, const uint4& th) {
    const __half2* h = (const __half2*)&u;
    const __half2* t = (const __half2*)&th;
    acc2[0] = __hfma2(h[0], t[0], acc2[0]);
    acc2[1] = __hfma2(h[1], t[1], acc2[1]);
    acc2[2] = __hfma2(h[2], t[2], acc2[2]);
    acc2[3] = __hfma2(h[3], t[3], acc2[3]);
}

__device__ __forceinline__ void grad8h(__half2* gj, const uint4& u, __half2 ch2) {
    const __half2* h = (const __half2*)&u;
    gj[0] = __hfma2(ch2, h[0], gj[0]);
    gj[1] = __hfma2(ch2, h[1], gj[1]);
    gj[2] = __hfma2(ch2, h[2], gj[2]);
    gj[3] = __hfma2(ch2, h[3], gj[3]);
}

__device__ __forceinline__ float acc4_to_float(const __half2* a) {
    float2 f0 = __half22float2(a[0]);
    float2 f1 = __half22float2(a[1]);
    float2 f2 = __half22float2(a[2]);
    float2 f3 = __half22float2(a[3]);
    return (f0.x + f0.y) + (f1.x + f1.y) + (f2.x + f2.y) + (f3.x + f3.y);
}

// R contiguous train rows; theta (fp16) read from smem. z identical on all
// lanes after the butterfly.
template<int R>
__device__ __forceinline__ void train_chunk(
    int n0, int lane, int t, const __half* s_th, __half2* hacc,
    const float* __restrict__ yn, const float* __restrict__ alphas)
{
    const uint4* xp[R];
#pragma unroll
    for (int r = 0; r < R; r++)
        xp[r] = (const uint4*)(g_xn_h + (size_t)(n0 + r) * DIMV);
    const uint4* tp = (const uint4*)s_th;
    const __half2 hz = __float2half2_rn(0.0f);
    __half2 a[R][4];
#pragma unroll
    for (int r = 0; r < R; r++) { a[r][0]=hz; a[r][1]=hz; a[r][2]=hz; a[r][3]=hz; }
#pragma unroll
    for (int j = 0; j < 8; j++) {
        uint4 th = tp[j*32+lane];               // conflict-free LDS.128
#pragma unroll
        for (int r = 0; r < R; r++) {
            uint4 u = xp[r][j*32+lane];
            dot8h(a[r], u, th);
        }
    }
    float z[R];
#pragma unroll
    for (int r = 0; r < R; r++) z[r] = acc4_to_float(a[r]);
#pragma unroll
    for (int o = 16; o; o >>= 1) {
#pragma unroll
        for (int r = 0; r < R; r++)
            z[r] += __shfl_xor_sync(0xffffffffu, z[r], o);
    }
    __half2 ch[R];
#pragma unroll
    for (int r = 0; r < R; r++) {
        float s = 1.0f / (1.0f + expf(-z[r]));
        float c = alphas[(size_t)t * NTR + (n0 + r)] * (s - yn[n0 + r]);
        ch[r] = __float2half2_rn(c);
    }
#pragma unroll
    for (int j = 0; j < 8; j++) {
#pragma unroll
        for (int r = 0; r < R; r++) {
            uint4 u = xp[r][j*32+lane];         // L1 hits
            grad8h(hacc + j*4, u, ch[r]);
        }
    }
}

// R contiguous dev rows; returns full loss sum of the R rows, identical on
// all lanes — caller must NOT reduce again.
template<int R>
__device__ __forceinline__ float dev_chunk(
    int m0, int lane, const __half* s_th, const float* __restrict__ dyn)
{
    const uint4* xp[R];
#pragma unroll
    for (int r = 0; r < R; r++)
        xp[r] = (const uint4*)(g_dxn_h + (size_t)(m0 + r) * DIMV);
    const uint4* tp = (const uint4*)s_th;
    const __half2 hz = __float2half2_rn(0.0f);
    __half2 a[R][4];
#pragma unroll
    for (int r = 0; r < R; r++) { a[r][0]=hz; a[r][1]=hz; a[r][2]=hz; a[r][3]=hz; }
#pragma unroll
    for (int j = 0; j < 8; j++) {
        uint4 th = tp[j*32+lane];
#pragma unroll
        for (int r = 0; r < R; r++) {
            uint4 u = xp[r][j*32+lane];
            dot8h(a[r], u, th);
        }
    }
    float z[R];
#pragma unroll
    for (int r = 0; r < R; r++) z[r] = acc4_to_float(a[r]);
#pragma unroll
    for (int o = 16; o; o >>= 1) {
#pragma unroll
        for (int r = 0; r < R; r++)
            z[r] += __shfl_xor_sync(0xffffffffu, z[r], o);
    }
    float s = 0.0f;
#pragma unroll
    for (int r = 0; r < R; r++) s += dev_loss_elem(z[r], dyn[m0 + r]);
    return s;
}

// ---------------------------------------------------------------------------
// Single persistent kernel: phase 0 = convert + zero state, then 500 steps.
__global__ void __launch_bounds__(NTHREADS, 1)
ak_all(const float* __restrict__ theta0,
       const float* __restrict__ xn,  const float* __restrict__ dxn,
       const float* __restrict__ yn,  const float* __restrict__ dyn,
       const float* __restrict__ alphas,
       float* __restrict__ out, int out_size) {
    extern __shared__ char smc[];
    float*  s_theta = (float*)smc;                               // 8 KB fp32
    __half* s_th2h  = (__half*)(smc + DIMV * 4);                 // 4 KB fp16
    __half* s_grad  = (__half*)(smc + DIMV * 4 + DIMV * 2);      // 64 KB
    float*  s_dev   = (float*)(smc + DIMV * 4 + DIMV * 2
                               + (size_t)NWARPS * DIMV * 2);     // 16 floats

    const int tid  = threadIdx.x;
    const int lane = tid & 31;
    const int w    = tid >> 5;
    const int cta  = blockIdx.x;
    const int ncta = gridDim.x;

    // ---------------- phase 0: fp32->fp16 convert + zero running totals ----
    {
        const size_t stride = (size_t)ncta * NTHREADS;
        const size_t gid    = (size_t)cta * NTHREADS + tid;
        const size_t n4 = (size_t)NTR * DIMV / 4;
        const size_t m4 = (size_t)MDEVR * DIMV / 4;
        const float4* s0 = (const float4*)xn;
        const float4* s1 = (const float4*)dxn;
        __half2* d0 = (__half2*)g_xn_h;
        __half2* d1 = (__half2*)g_dxn_h;
        for (size_t i = gid; i < n4; i += stride) {
            float4 v = s0[i];
            d0[2*i+0] = __floats2half2_rn(v.x, v.y);
            d0[2*i+1] = __floats2half2_rn(v.z, v.w);
        }
        for (size_t i = gid; i < m4; i += stride) {
            float4 v = s1[i];
            d1[2*i+0] = __floats2half2_rn(v.x, v.y);
            d1[2*i+1] = __floats2half2_rn(v.z, v.w);
        }
        if (gid < DIMV) g_gradacc[gid] = 0ull;
        if (gid == DIMV) g_devacc = 0ull;
        for (size_t j = TST + 1 + gid; j < (size_t)out_size; j += stride)
            out[j] = 0.0f;
    }
    for (int d = tid; d < DIMV; d += NTHREADS) s_theta[d] = theta0[d];
    grid_barrier((unsigned)ncta);   // conversions + zeroing visible everywhere

    // CTA / warp row ranges (exact split, imbalance <= 1 row)
    const int rb = (int)(((long long)cta * NTR) / ncta);
    const int re = (int)(((long long)(cta + 1) * NTR) / ncta);
    const int mb = (int)(((long long)cta * MDEVR) / ncta);
    const int me = (int)(((long long)(cta + 1) * MDEVR) / ncta);
    const int twb = rb + (int)(((long long)(re - rb) * w) / NWARPS);
    const int twe = rb + (int)(((long long)(re - rb) * (w + 1)) / NWARPS);
    const int dwb = mb + (int)(((long long)(me - mb) * w) / NWARPS);
    const int dwe = mb + (int)(((long long)(me - mb) * (w + 1)) / NWARPS);

    long long prev[4];   // running-total snapshots for dims [tid*4, tid*4+4)
#pragma unroll
    for (int i = 0; i < 4; i++) prev[i] = 0ll;
    long long devprev = 0ll;
    float isum = 0.0f;   // cta0/tid0 only
    const __half2 hz = __float2half2_rn(0.0f);

    for (int t = 0; t < TST; ++t) {
        // ---- refresh fp16 theta in smem (512 threads x 4 dims = 2048)
        {
            float4 v = ((const float4*)s_theta)[tid];
            __half2 h0 = __floats2half2_rn(v.x, v.y);
            __half2 h1 = __floats2half2_rn(v.z, v.w);
            uint2 u; u.x = *(unsigned*)&h0; u.y = *(unsigned*)&h1;
            ((uint2*)s_th2h)[tid] = u;
        }
        __syncthreads();

        // ---- train rows (pair -> single)
        __half2 hacc[32];
#pragma unroll
        for (int j = 0; j < 32; j++) hacc[j] = hz;
        {
            int n = twb;
            for (; n + 2 <= twe; n += 2) train_chunk<2>(n, lane, t, s_th2h, hacc, yn, alphas);
            if (n < twe)                 train_chunk<1>(n, lane, t, s_th2h, hacc, yn, alphas);
        }
        {
            uint4* gp4 = (uint4*)(s_grad + (size_t)w * DIMV);
#pragma unroll
            for (int j = 0; j < 8; j++) {
                uint4 u;
                ((__half2*)&u)[0] = hacc[j*4+0];
                ((__half2*)&u)[1] = hacc[j*4+1];
                ((__half2*)&u)[2] = hacc[j*4+2];
                ((__half2*)&u)[3] = hacc[j*4+3];
                gp4[j*32+lane] = u;
            }
        }

        // ---- dev loss with theta_t (= full_losses[t]); dsum all-lane-identical
        float dsum = 0.0f;
        {
            int m = dwb;
            for (; m + 2 <= dwe; m += 2) dsum += dev_chunk<2>(m, lane, s_th2h, dyn);
            if (m < dwe)                 dsum += dev_chunk<1>(m, lane, s_th2h, dyn);
        }
        if (lane == 0) s_dev[w] = dsum;
        __syncthreads();

        // ---- CTA reduce + fixed-point atomics into running totals
        if (tid == 0) {
            float s = 0.0f;
#pragma unroll
            for (int i = 0; i < NWARPS; i++) s += s_dev[i];
            atomicAdd(&g_devacc, (unsigned long long)llrintf(s * S_DEV_F));
        }
        {
            const __half2* sg2 = (const __half2*)s_grad;
#pragma unroll
            for (int i = 0; i < 2; i++) {           // (DIMV/2)/NTHREADS = 2
                int idx = tid + i * NTHREADS;
                float2 s = make_float2(0.0f, 0.0f);
#pragma unroll
                for (int ww = 0; ww < NWARPS; ww++) {
                    float2 f = __half22float2(sg2[ww * (DIMV/2) + idx]);
                    s.x += f.x; s.y += f.y;
                }
                atomicAdd(&g_gradacc[2*idx+0], (unsigned long long)llrintf(s.x * S_GRAD_F));
                atomicAdd(&g_gradacc[2*idx+1], (unsigned long long)llrintf(s.y * S_GRAD_F));
            }
        }

        grid_barrier((unsigned)ncta);

        // ---- apply delta; every CTA updates its smem theta identically
        {
            const long long* ga = (const long long*)g_gradacc;
#pragma unroll
            for (int i = 0; i < 4; i++) {
                int d = tid * 4 + i;
                long long v = ga[d];
                float g = (float)(v - prev[i]) * INV_SGRAD;
                prev[i] = v;
                s_theta[d] -= ETA * g;
            }
            if (cta == 0 && tid == 0) {
                long long dv = (long long)g_devacc;
                float Lt = (float)(dv - devprev) * INV_SDEV * (1.0f / MDEVR);
                devprev = dv;
                if (1 + t < out_size) out[1 + t] = Lt;
                if (t >= 1) isum += Lt;
            }
        }
        __syncthreads();
    }

    // ---- final dev eval at theta_T; finalize scalar loss
    {
        float4 v = ((const float4*)s_theta)[tid];
        __half2 h0 = __floats2half2_rn(v.x, v.y);
        __half2 h1 = __floats2half2_rn(v.z, v.w);
        uint2 u; u.x = *(unsigned*)&h0; u.y = *(unsigned*)&h1;
        ((uint2*)s_th2h)[tid] = u;
    }
    __syncthreads();
    {
        float dsum = 0.0f;
        int m = dwb;
        for (; m + 2 <= dwe; m += 2) dsum += dev_chunk<2>(m, lane, s_th2h, dyn);
        if (m < dwe)                 dsum += dev_chunk<1>(m, lane, s_th2h, dyn);
        if (lane == 0) s_dev[w] = dsum;
        __syncthreads();
        if (tid == 0) {
            float s = 0.0f;
#pragma unroll
            for (int i = 0; i < NWARPS; i++) s += s_dev[i];
            atomicAdd(&g_devacc, (unsigned long long)llrintf(s * S_DEV_F));
        }
        grid_barrier((unsigned)ncta);
        if (cta == 0 && tid == 0) {
            long long dv = (long long)g_devacc;
            float LT = (float)(dv - devprev) * INV_SDEV * (1.0f / MDEVR);
            if (out_size > 0) out[0] = (isum + LT) / (float)TST;
        }
    }
}

// ---------------------------------------------------------------------------
extern "C" void kernel_launch(void* const* d_in, const int* in_sizes, int n_in,
                              void* d_out, int out_size) {
    const float *theta = nullptr, *alphas = nullptr, *xn = nullptr,
                *yn = nullptr, *dxn = nullptr, *dyn = nullptr;
    for (int i = 0; i < n_in; i++) {
        switch (in_sizes[i]) {
            case DIMV:         theta  = (const float*)d_in[i]; break;
            case TST * NTR:    alphas = (const float*)d_in[i]; break;
            case NTR * DIMV:   xn     = (const float*)d_in[i]; break;
            case NTR:          yn     = (const float*)d_in[i]; break;
            case MDEVR * DIMV: dxn    = (const float*)d_in[i]; break;
            case MDEVR:        dyn    = (const float*)d_in[i]; break;
            default: break;
        }
    }
    float* out = (float*)d_out;

    int dev = 0;
    cudaGetDevice(&dev);
    int nsm = 148;
    cudaDeviceGetAttribute(&nsm, cudaDevAttrMultiProcessorCount, dev);
    int ncta = nsm < 1 ? 1 : nsm;

    size_t smem = (size_t)DIMV * 4            // s_theta fp32
                + (size_t)DIMV * 2            // s_th2h fp16
                + (size_t)NWARPS * DIMV * 2   // s_grad
                + NWARPS * sizeof(float);     // s_dev   (~76.1 KB)
    cudaFuncSetAttribute(ak_all, cudaFuncAttributeMaxDynamicSharedMemorySize,
                         (int)smem);

    ak_all<<<ncta, NTHREADS, smem>>>(theta, xn, dxn, yn, dyn, alphas,
                                     out, out_size);
}